// round 3
// baseline (speedup 1.0000x reference)
#include <cuda_runtime.h>
#include <cuda_bf16.h>
#include <math.h>

// Problem constants
#define BB      2
#define TT      2048
#define NH      16
#define HD      128
#define NE      2048            // n_embed
#define QKV_LD  2304            // (NH+2)*HD
#define MROWS   (BB*TT)         // 4096

// Scratch (allocation-free rule: __device__ globals)
__device__ float g_qkv[(size_t)MROWS * QKV_LD];   // 37.7 MB
__device__ float g_att[(size_t)MROWS * NE];       // 33.6 MB

// ---------------------------------------------------------------------------
// SGEMM: C[M,N] = A[M,K] @ B[N,K]^T  (both operands row-major, K contiguous)
// BM=BN=128, BK=16, 256 threads, 8x8 per thread. Dims divide exactly; no guards.
// ---------------------------------------------------------------------------
__global__ __launch_bounds__(256) void sgemm_nt(const float* __restrict__ A,
                                                const float* __restrict__ B,
                                                float* __restrict__ C,
                                                int K, int ldc) {
    __shared__ float As[16 * 132];
    __shared__ float Bs[16 * 132];

    const int tid = threadIdx.x;
    const int tx = tid & 15;          // col group
    const int ty = tid >> 4;          // row group
    const int m0 = blockIdx.y * 128;
    const int n0 = blockIdx.x * 128;

    const float* Ab = A + (size_t)m0 * K;
    const float* Bb = B + (size_t)n0 * K;

    float acc[8][8];
#pragma unroll
    for (int i = 0; i < 8; i++)
#pragma unroll
        for (int j = 0; j < 8; j++) acc[i][j] = 0.0f;

    for (int k0 = 0; k0 < K; k0 += 16) {
        __syncthreads();
#pragma unroll
        for (int i = 0; i < 2; i++) {
            int f = tid + i * 256;          // 0..511
            int r = f >> 2;                 // 0..127
            int kq = (f & 3) * 4;           // 0,4,8,12
            float4 a = *(const float4*)&Ab[(size_t)r * K + k0 + kq];
            As[(kq + 0) * 132 + r] = a.x;
            As[(kq + 1) * 132 + r] = a.y;
            As[(kq + 2) * 132 + r] = a.z;
            As[(kq + 3) * 132 + r] = a.w;
            float4 b = *(const float4*)&Bb[(size_t)r * K + k0 + kq];
            Bs[(kq + 0) * 132 + r] = b.x;
            Bs[(kq + 1) * 132 + r] = b.y;
            Bs[(kq + 2) * 132 + r] = b.z;
            Bs[(kq + 3) * 132 + r] = b.w;
        }
        __syncthreads();
#pragma unroll 8
        for (int kk = 0; kk < 16; kk++) {
            float4 a0 = *(const float4*)&As[kk * 132 + ty * 8];
            float4 a1 = *(const float4*)&As[kk * 132 + ty * 8 + 4];
            float4 b0 = *(const float4*)&Bs[kk * 132 + tx * 8];
            float4 b1 = *(const float4*)&Bs[kk * 132 + tx * 8 + 4];
            float ar[8] = {a0.x, a0.y, a0.z, a0.w, a1.x, a1.y, a1.z, a1.w};
            float br[8] = {b0.x, b0.y, b0.z, b0.w, b1.x, b1.y, b1.z, b1.w};
#pragma unroll
            for (int i = 0; i < 8; i++)
#pragma unroll
                for (int j = 0; j < 8; j++)
                    acc[i][j] = fmaf(ar[i], br[j], acc[i][j]);
        }
    }

#pragma unroll
    for (int i = 0; i < 8; i++) {
        size_t off = (size_t)(m0 + ty * 8 + i) * ldc + n0 + tx * 8;
        float4 c0 = make_float4(acc[i][0], acc[i][1], acc[i][2], acc[i][3]);
        float4 c1 = make_float4(acc[i][4], acc[i][5], acc[i][6], acc[i][7]);
        *(float4*)&C[off]     = c0;
        *(float4*)&C[off + 4] = c1;
    }
}

// ---------------------------------------------------------------------------
// RoPE in-place on q (16 heads) and k (1 head) of g_qkv.
// Reference: pos = 10000 ** ((-2*i - 1)/128) for i in arange(0, 128, 2),
// i.e. for frequency index j (=threadIdx): exponent = -(4j + 1)/128.
// ---------------------------------------------------------------------------
__global__ __launch_bounds__(64) void rope_kernel() {
    const int row = blockIdx.x;           // 0..4095   (b*T + t)
    const int t = row & (TT - 1);
    const int j = threadIdx.x;            // 0..63 frequency index

    // pos[j] = 10000 ** (-(4j+1)/128)
    double e = ((-4.0 * (double)j - 1.0) / 128.0) * 9.210340371976184; // ln(1e4)
    float freq = (float)exp(e);
    float ang = (float)t * freq;
    float c = cosf(ang);
    float s = sinf(ang);

    float* base = g_qkv + (size_t)row * QKV_LD;
#pragma unroll
    for (int seg = 0; seg < 17; seg++) {   // 16 q heads + k
        float* p = base + seg * 128;
        float x1 = p[j];
        float x2 = p[j + 64];
        p[j]      = x1 * c - x2 * s;
        p[j + 64] = x2 * c + x1 * s;
    }
}

// ---------------------------------------------------------------------------
// Flash-style MQA: per (b, h, 64 q rows) CTA; loop over 32 chunks of 64 keys.
// Smem: Qt[128][68] (d-major, pre-scaled), Kt[128][68], Vs[64][128], Ps[64][68]
// 256 threads as 16x16; S tile 4x4/thread, O tile 4x8/thread. Conflict-free LDS.
// ---------------------------------------------------------------------------
#define FLASH_SMEM ((128*68 + 128*68 + 64*128 + 64*68) * 4)

__global__ __launch_bounds__(256) void mqa_flash() {
    const int b = blockIdx.z;
    const int h = blockIdx.y;
    const int m0 = blockIdx.x * 64;

    extern __shared__ float sm[];
    float* Qt = sm;                  // 128*68
    float* Kt = Qt + 128 * 68;       // 128*68
    float* Vs = Kt + 128 * 68;       // 64*128
    float* Ps = Vs + 64 * 128;       // 64*68

    const int tid = threadIdx.x;
    const int tx = tid & 15;
    const int ty = tid >> 4;
    const float scale = 0.08838834764831845f;  // 1/sqrt(128)

    // Load Q tile transposed (d-major), pre-scaled
#pragma unroll
    for (int i = 0; i < 8; i++) {
        int f = tid + i * 256;
        int r = f >> 5;                 // 0..63
        int c4 = (f & 31) * 4;          // 0..124
        const float4 v = *(const float4*)
            &g_qkv[(size_t)(b * TT + m0 + r) * QKV_LD + h * 128 + c4];
        Qt[(c4 + 0) * 68 + r] = v.x * scale;
        Qt[(c4 + 1) * 68 + r] = v.y * scale;
        Qt[(c4 + 2) * 68 + r] = v.z * scale;
        Qt[(c4 + 3) * 68 + r] = v.w * scale;
    }

    float acc[4][8];
#pragma unroll
    for (int i = 0; i < 4; i++)
#pragma unroll
        for (int j = 0; j < 8; j++) acc[i][j] = 0.0f;
    float m_i[4], l_i[4];
#pragma unroll
    for (int i = 0; i < 4; i++) { m_i[i] = -INFINITY; l_i[i] = 0.0f; }

    for (int kb = 0; kb < 32; kb++) {
        __syncthreads();   // previous PV / Ps usage done before overwrite
        // Load K chunk transposed + V chunk row-major
#pragma unroll
        for (int i = 0; i < 8; i++) {
            int f = tid + i * 256;
            int r = f >> 5;
            int c4 = (f & 31) * 4;
            size_t row = (size_t)(b * TT + kb * 64 + r) * QKV_LD;
            float4 kv = *(const float4*)&g_qkv[row + 2048 + c4];
            Kt[(c4 + 0) * 68 + r] = kv.x;
            Kt[(c4 + 1) * 68 + r] = kv.y;
            Kt[(c4 + 2) * 68 + r] = kv.z;
            Kt[(c4 + 3) * 68 + r] = kv.w;
            *(float4*)&Vs[r * 128 + c4] = *(const float4*)&g_qkv[row + 2176 + c4];
        }
        __syncthreads();

        // S = (Q*scale) @ K^T : 4x4 per thread
        float s[4][4];
#pragma unroll
        for (int i = 0; i < 4; i++)
#pragma unroll
            for (int j = 0; j < 4; j++) s[i][j] = 0.0f;

#pragma unroll 8
        for (int d = 0; d < 128; d++) {
            float4 aq = *(const float4*)&Qt[d * 68 + 4 * ty];
            float4 bk = *(const float4*)&Kt[d * 68 + 4 * tx];
            float ar[4] = {aq.x, aq.y, aq.z, aq.w};
            float br[4] = {bk.x, bk.y, bk.z, bk.w};
#pragma unroll
            for (int i = 0; i < 4; i++)
#pragma unroll
                for (int j = 0; j < 4; j++)
                    s[i][j] = fmaf(ar[i], br[j], s[i][j]);
        }

        // Online softmax update (row groups live on 16 lanes sharing ty)
#pragma unroll
        for (int i = 0; i < 4; i++) {
            float rm = fmaxf(fmaxf(s[i][0], s[i][1]), fmaxf(s[i][2], s[i][3]));
            rm = fmaxf(rm, __shfl_xor_sync(0xffffffffu, rm, 1));
            rm = fmaxf(rm, __shfl_xor_sync(0xffffffffu, rm, 2));
            rm = fmaxf(rm, __shfl_xor_sync(0xffffffffu, rm, 4));
            rm = fmaxf(rm, __shfl_xor_sync(0xffffffffu, rm, 8));
            float mn = fmaxf(m_i[i], rm);
            float corr = __expf(m_i[i] - mn);
            m_i[i] = mn;
            float rs = 0.0f;
#pragma unroll
            for (int j = 0; j < 4; j++) {
                s[i][j] = __expf(s[i][j] - mn);
                rs += s[i][j];
            }
            rs += __shfl_xor_sync(0xffffffffu, rs, 1);
            rs += __shfl_xor_sync(0xffffffffu, rs, 2);
            rs += __shfl_xor_sync(0xffffffffu, rs, 4);
            rs += __shfl_xor_sync(0xffffffffu, rs, 8);
            l_i[i] = l_i[i] * corr + rs;
#pragma unroll
            for (int j = 0; j < 8; j++) acc[i][j] *= corr;
            *(float4*)&Ps[(4 * ty + i) * 68 + 4 * tx] =
                make_float4(s[i][0], s[i][1], s[i][2], s[i][3]);
        }
        __syncthreads();

        // O += P @ V : rows 4*ty+i, cols tx*8..tx*8+7
#pragma unroll 4
        for (int kk4 = 0; kk4 < 16; kk4++) {
            float4 p4[4];
#pragma unroll
            for (int i = 0; i < 4; i++)
                p4[i] = *(const float4*)&Ps[(4 * ty + i) * 68 + kk4 * 4];
#pragma unroll
            for (int u = 0; u < 4; u++) {
                const float* vrow = &Vs[(kk4 * 4 + u) * 128 + tx * 8];
                float4 v0 = *(const float4*)&vrow[0];
                float4 v1 = *(const float4*)&vrow[4];
                float vv[8] = {v0.x, v0.y, v0.z, v0.w, v1.x, v1.y, v1.z, v1.w};
#pragma unroll
                for (int i = 0; i < 4; i++) {
                    float p = (u == 0) ? p4[i].x : (u == 1) ? p4[i].y
                            : (u == 2) ? p4[i].z : p4[i].w;
#pragma unroll
                    for (int j = 0; j < 8; j++)
                        acc[i][j] = fmaf(p, vv[j], acc[i][j]);
                }
            }
        }
    }

    // Epilogue: divide by l, store to [B,T,H,hd]
#pragma unroll
    for (int i = 0; i < 4; i++) {
        float inv = 1.0f / l_i[i];
        size_t off = (size_t)(b * TT + m0 + 4 * ty + i) * NE + h * 128 + tx * 8;
        float4 o0 = make_float4(acc[i][0] * inv, acc[i][1] * inv,
                                acc[i][2] * inv, acc[i][3] * inv);
        float4 o1 = make_float4(acc[i][4] * inv, acc[i][5] * inv,
                                acc[i][6] * inv, acc[i][7] * inv);
        *(float4*)&g_att[off]     = o0;
        *(float4*)&g_att[off + 4] = o1;
    }
}

// ---------------------------------------------------------------------------
extern "C" void kernel_launch(void* const* d_in, const int* in_sizes, int n_in,
                              void* d_out, int out_size) {
    const float* x      = (const float*)d_in[0];   // [2,2048,2048]
    const float* w_attn = (const float*)d_in[1];   // [2304,2048]
    const float* w_out  = (const float*)d_in[2];   // [2048,2048]
    float* out = (float*)d_out;                    // [2,2048,2048]

    float* qkv = nullptr;
    float* att = nullptr;
    cudaGetSymbolAddress((void**)&qkv, g_qkv);
    cudaGetSymbolAddress((void**)&att, g_att);

    cudaFuncSetAttribute(mqa_flash,
                         cudaFuncAttributeMaxDynamicSharedMemorySize, FLASH_SMEM);

    // 1) qkv = x @ w_attn^T   [4096 x 2304]
    sgemm_nt<<<dim3(QKV_LD / 128, MROWS / 128), 256>>>(x, w_attn, qkv, NE, QKV_LD);

    // 2) RoPE on q and k in place
    rope_kernel<<<MROWS, 64>>>();

    // 3) attention -> g_att [B,T,H,hd]
    mqa_flash<<<dim3(TT / 64, NH, BB), 256, FLASH_SMEM>>>();

    // 4) out = att @ w_out^T  [4096 x 2048]
    sgemm_nt<<<dim3(NE / 128, MROWS / 128), 256>>>(att, w_out, out, NE, NE);
}

// round 5
// speedup vs baseline: 1.3292x; 1.3292x over previous
#include <cuda_runtime.h>
#include <cuda_bf16.h>
#include <math.h>
#include <stdint.h>

// Problem constants
#define BB      2
#define TT      2048
#define NH      16
#define HD      128
#define NE      2048
#define QKV_LD  2304
#define MROWS   (BB*TT)         // 4096
#define KDIM    2048

// Scratch (__device__ globals; no allocation allowed)
__device__ float g_qkv[(size_t)MROWS * QKV_LD];
__device__ __nv_bfloat16 g_xh[(size_t)MROWS * NE];
__device__ __nv_bfloat16 g_xl[(size_t)MROWS * NE];
__device__ __nv_bfloat16 g_wah[(size_t)QKV_LD * NE];
__device__ __nv_bfloat16 g_wal[(size_t)QKV_LD * NE];
__device__ __nv_bfloat16 g_woh[(size_t)NE * NE];
__device__ __nv_bfloat16 g_wol[(size_t)NE * NE];
__device__ __nv_bfloat16 g_ath[(size_t)MROWS * NE];
__device__ __nv_bfloat16 g_atl[(size_t)MROWS * NE];

// ---------------------------------------------------------------------------
// Helpers: smem addr, ldmatrix, mma.sync (bf16), cp.async
// ---------------------------------------------------------------------------
__device__ __forceinline__ uint32_t smem_u32(const void* p) {
    uint32_t a;
    asm("{ .reg .u64 t; cvta.to.shared.u64 t, %1; cvt.u32.u64 %0, t; }"
        : "=r"(a) : "l"(p));
    return a;
}

__device__ __forceinline__ void ldsm_x4(uint32_t& r0, uint32_t& r1,
                                        uint32_t& r2, uint32_t& r3,
                                        uint32_t addr) {
    asm volatile("ldmatrix.sync.aligned.m8n8.x4.shared.b16 {%0,%1,%2,%3}, [%4];"
                 : "=r"(r0), "=r"(r1), "=r"(r2), "=r"(r3) : "r"(addr));
}

__device__ __forceinline__ void mma_16816(float* d, const uint32_t* a,
                                          const uint32_t* b) {
    asm volatile(
        "mma.sync.aligned.m16n8k16.row.col.f32.bf16.bf16.f32 "
        "{%0,%1,%2,%3}, {%4,%5,%6,%7}, {%8,%9}, {%0,%1,%2,%3};"
        : "+f"(d[0]), "+f"(d[1]), "+f"(d[2]), "+f"(d[3])
        : "r"(a[0]), "r"(a[1]), "r"(a[2]), "r"(a[3]), "r"(b[0]), "r"(b[1]));
}

#define CP_ASYNC16(dst, src) \
    asm volatile("cp.async.cg.shared.global [%0], [%1], 16;" :: "r"(dst), "l"(src))

// ---------------------------------------------------------------------------
// Split fp32 -> (hi, lo) bf16
// ---------------------------------------------------------------------------
__global__ __launch_bounds__(256) void split_kernel(const float* __restrict__ src,
                                                    __nv_bfloat16* __restrict__ hi,
                                                    __nv_bfloat16* __restrict__ lo,
                                                    int n4) {
    int i = blockIdx.x * 256 + threadIdx.x;
    if (i >= n4) return;
    float4 v = ((const float4*)src)[i];
    __nv_bfloat16 h0 = __float2bfloat16(v.x);
    __nv_bfloat16 h1 = __float2bfloat16(v.y);
    __nv_bfloat16 h2 = __float2bfloat16(v.z);
    __nv_bfloat16 h3 = __float2bfloat16(v.w);
    __nv_bfloat16 l0 = __float2bfloat16(v.x - __bfloat162float(h0));
    __nv_bfloat16 l1 = __float2bfloat16(v.y - __bfloat162float(h1));
    __nv_bfloat16 l2 = __float2bfloat16(v.z - __bfloat162float(h2));
    __nv_bfloat16 l3 = __float2bfloat16(v.w - __bfloat162float(h3));
    __nv_bfloat162* hp = (__nv_bfloat162*)hi;
    __nv_bfloat162* lp = (__nv_bfloat162*)lo;
    hp[2 * i]     = __nv_bfloat162(h0, h1);
    hp[2 * i + 1] = __nv_bfloat162(h2, h3);
    lp[2 * i]     = __nv_bfloat162(l0, l1);
    lp[2 * i + 1] = __nv_bfloat162(l2, l3);
}

// ---------------------------------------------------------------------------
// Warp-mma split-bf16 GEMM: C[M,N] = (Ah+Al)[M,K] @ (Bh+Bl)[N,K]^T (fp32 acc)
// C = Ah*Bh + Ah*Bl + Al*Bh. CTA tile 128x128, K-tile 64, 2-stage cp.async.
// 8 warps as 4(M) x 2(N); warp tile 32x64 = 2x8 mma tiles of 16x8.
// Smem rows padded to 144B -> ldmatrix conflict-free.
// ---------------------------------------------------------------------------
#define GKT 64
#define GNT (KDIM / GKT)                 // 32 k-tiles
#define ROWB 144                         // smem row stride (bytes)
#define TILE_B (128 * ROWB)              // 18432
#define STAGE_B (4 * TILE_B)             // Ah, Al, Bh, Bl
#define GEMM_SMEM (2 * STAGE_B)          // 147456

__global__ __launch_bounds__(256, 1) void gemm_bf16x3(
    const __nv_bfloat16* __restrict__ Ah, const __nv_bfloat16* __restrict__ Al,
    const __nv_bfloat16* __restrict__ Bh, const __nv_bfloat16* __restrict__ Bl,
    float* __restrict__ C, int ldc) {
    extern __shared__ char dynsmem[];
    const uint32_t sbase0 = smem_u32(dynsmem);

    const int tid = threadIdx.x;
    const int lane = tid & 31;
    const int warp = tid >> 5;
    const int wm = warp & 3;             // 0..3 (M)
    const int wn = warp >> 2;            // 0..1 (N)
    const int m0 = blockIdx.y * 128;
    const int n0 = blockIdx.x * 128;

    const __nv_bfloat16* srcs[4] = {
        Ah + (size_t)m0 * KDIM, Al + (size_t)m0 * KDIM,
        Bh + (size_t)n0 * KDIM, Bl + (size_t)n0 * KDIM};

    auto load_stage = [&](int s, int kt) {
#pragma unroll
        for (int i = 0; i < 16; i++) {
            const int t = i >> 2;                      // tile 0..3
            const int f = (i & 3) * 256 + tid;         // 0..1023
            const int r = f >> 3;                      // row 0..127
            const int c = f & 7;                       // 16B chunk
            const __nv_bfloat16* g = srcs[t] + (size_t)r * KDIM + kt * GKT + c * 8;
            uint32_t d = sbase0 + s * STAGE_B + t * TILE_B + r * ROWB + c * 16;
            CP_ASYNC16(d, g);
        }
        asm volatile("cp.async.commit_group;" ::: "memory");
    };

    float acc[16][4];                    // [mi*8 + nj][4]
#pragma unroll
    for (int t = 0; t < 16; t++)
#pragma unroll
        for (int j = 0; j < 4; j++) acc[t][j] = 0.0f;

    load_stage(0, 0);

    for (int kt = 0; kt < GNT; kt++) {
        const int s = kt & 1;
        if (kt + 1 < GNT) {
            load_stage((kt + 1) & 1, kt + 1);
            asm volatile("cp.async.wait_group 1;" ::: "memory");
        } else {
            asm volatile("cp.async.wait_group 0;" ::: "memory");
        }
        __syncthreads();

        const uint32_t st = sbase0 + s * STAGE_B;
        const uint32_t aBh = st + (wm * 32) * ROWB;               // Ah tile
        const uint32_t aBl = aBh + TILE_B;                        // Al tile
        const uint32_t bBh = st + 2 * TILE_B + (wn * 64) * ROWB;  // Bh tile
        const uint32_t bBl = bBh + TILE_B;                        // Bl tile

#pragma unroll
        for (int ks = 0; ks < 4; ks++) {
            const uint32_t kc = ks * 32 + (lane >> 4) * 16;       // A col bytes
            uint32_t ah[2][4], al[2][4];
#pragma unroll
            for (int mi = 0; mi < 2; mi++) {
                uint32_t ao = (mi * 16 + (lane & 15)) * ROWB + kc;
                ldsm_x4(ah[mi][0], ah[mi][1], ah[mi][2], ah[mi][3], aBh + ao);
                ldsm_x4(al[mi][0], al[mi][1], al[mi][2], al[mi][3], aBl + ao);
            }
            // B: lane -> mat = lane/8 (0..3), row_in = lane%8
            // mat layout per x4: (n0-7,k0-7)(n0-7,k8-15)(n8-15,k0-7)(n8-15,k8-15)
            const int mat = lane >> 3;
            const uint32_t bo = ((mat >> 1) * 8 + (lane & 7)) * ROWB
                              + ks * 32 + (mat & 1) * 16;
            uint32_t bh[8][2], bl[8][2];
#pragma unroll
            for (int g = 0; g < 4; g++) {
                uint32_t o = g * 16 * ROWB + bo;
                ldsm_x4(bh[2 * g][0], bh[2 * g][1], bh[2 * g + 1][0],
                        bh[2 * g + 1][1], bBh + o);
                ldsm_x4(bl[2 * g][0], bl[2 * g][1], bl[2 * g + 1][0],
                        bl[2 * g + 1][1], bBl + o);
            }
#pragma unroll
            for (int mi = 0; mi < 2; mi++)
#pragma unroll
                for (int nj = 0; nj < 8; nj++) {
                    mma_16816(acc[mi * 8 + nj], ah[mi], bh[nj]);
                    mma_16816(acc[mi * 8 + nj], ah[mi], bl[nj]);
                    mma_16816(acc[mi * 8 + nj], al[mi], bh[nj]);
                }
        }
        __syncthreads();   // all reads of stage s done before it is reloaded
    }

    // Epilogue: d0,d1 -> (row = lane/4, col = 2*(lane%4)), d2,d3 -> row+8
    const int rbase = m0 + wm * 32 + (lane >> 2);
    const int cbase = n0 + wn * 64 + (lane & 3) * 2;
#pragma unroll
    for (int mi = 0; mi < 2; mi++)
#pragma unroll
        for (int nj = 0; nj < 8; nj++) {
            float* c0 = C + (size_t)(rbase + mi * 16) * ldc + cbase + nj * 8;
            float* c1 = c0 + 8 * ldc;
            *(float2*)c0 = make_float2(acc[mi * 8 + nj][0], acc[mi * 8 + nj][1]);
            *(float2*)c1 = make_float2(acc[mi * 8 + nj][2], acc[mi * 8 + nj][3]);
        }
}

// ---------------------------------------------------------------------------
// RoPE (verified): pos[j] = 10000 ** (-(4j+1)/128)
// ---------------------------------------------------------------------------
__global__ __launch_bounds__(64) void rope_kernel() {
    const int row = blockIdx.x;
    const int t = row & (TT - 1);
    const int j = threadIdx.x;

    double e = ((-4.0 * (double)j - 1.0) / 128.0) * 9.210340371976184;
    float freq = (float)exp(e);
    float ang = (float)t * freq;
    float c = cosf(ang);
    float s = sinf(ang);

    float* base = g_qkv + (size_t)row * QKV_LD;
#pragma unroll
    for (int seg = 0; seg < 17; seg++) {
        float* p = base + seg * 128;
        float x1 = p[j];
        float x2 = p[j + 64];
        p[j]      = x1 * c - x2 * s;
        p[j + 64] = x2 * c + x1 * s;
    }
}

// ---------------------------------------------------------------------------
// Flash-style MQA (verified round 3); epilogue emits hi/lo bf16 att.
// ---------------------------------------------------------------------------
#define FLASH_SMEM ((128*68 + 128*68 + 64*128 + 64*68) * 4)

__global__ __launch_bounds__(256) void mqa_flash() {
    const int b = blockIdx.z;
    const int h = blockIdx.y;
    const int m0 = blockIdx.x * 64;

    extern __shared__ float sm[];
    float* Qt = sm;
    float* Kt = Qt + 128 * 68;
    float* Vs = Kt + 128 * 68;
    float* Ps = Vs + 64 * 128;

    const int tid = threadIdx.x;
    const int tx = tid & 15;
    const int ty = tid >> 4;
    const float scale = 0.08838834764831845f;

#pragma unroll
    for (int i = 0; i < 8; i++) {
        int f = tid + i * 256;
        int r = f >> 5;
        int c4 = (f & 31) * 4;
        const float4 v = *(const float4*)
            &g_qkv[(size_t)(b * TT + m0 + r) * QKV_LD + h * 128 + c4];
        Qt[(c4 + 0) * 68 + r] = v.x * scale;
        Qt[(c4 + 1) * 68 + r] = v.y * scale;
        Qt[(c4 + 2) * 68 + r] = v.z * scale;
        Qt[(c4 + 3) * 68 + r] = v.w * scale;
    }

    float acc[4][8];
#pragma unroll
    for (int i = 0; i < 4; i++)
#pragma unroll
        for (int j = 0; j < 8; j++) acc[i][j] = 0.0f;
    float m_i[4], l_i[4];
#pragma unroll
    for (int i = 0; i < 4; i++) { m_i[i] = -INFINITY; l_i[i] = 0.0f; }

    for (int kb = 0; kb < 32; kb++) {
        __syncthreads();
#pragma unroll
        for (int i = 0; i < 8; i++) {
            int f = tid + i * 256;
            int r = f >> 5;
            int c4 = (f & 31) * 4;
            size_t row = (size_t)(b * TT + kb * 64 + r) * QKV_LD;
            float4 kv = *(const float4*)&g_qkv[row + 2048 + c4];
            Kt[(c4 + 0) * 68 + r] = kv.x;
            Kt[(c4 + 1) * 68 + r] = kv.y;
            Kt[(c4 + 2) * 68 + r] = kv.z;
            Kt[(c4 + 3) * 68 + r] = kv.w;
            *(float4*)&Vs[r * 128 + c4] = *(const float4*)&g_qkv[row + 2176 + c4];
        }
        __syncthreads();

        float s[4][4];
#pragma unroll
        for (int i = 0; i < 4; i++)
#pragma unroll
            for (int j = 0; j < 4; j++) s[i][j] = 0.0f;

#pragma unroll 8
        for (int d = 0; d < 128; d++) {
            float4 aq = *(const float4*)&Qt[d * 68 + 4 * ty];
            float4 bk = *(const float4*)&Kt[d * 68 + 4 * tx];
            float ar[4] = {aq.x, aq.y, aq.z, aq.w};
            float br[4] = {bk.x, bk.y, bk.z, bk.w};
#pragma unroll
            for (int i = 0; i < 4; i++)
#pragma unroll
                for (int j = 0; j < 4; j++)
                    s[i][j] = fmaf(ar[i], br[j], s[i][j]);
        }

#pragma unroll
        for (int i = 0; i < 4; i++) {
            float rm = fmaxf(fmaxf(s[i][0], s[i][1]), fmaxf(s[i][2], s[i][3]));
            rm = fmaxf(rm, __shfl_xor_sync(0xffffffffu, rm, 1));
            rm = fmaxf(rm, __shfl_xor_sync(0xffffffffu, rm, 2));
            rm = fmaxf(rm, __shfl_xor_sync(0xffffffffu, rm, 4));
            rm = fmaxf(rm, __shfl_xor_sync(0xffffffffu, rm, 8));
            float mn = fmaxf(m_i[i], rm);
            float corr = __expf(m_i[i] - mn);
            m_i[i] = mn;
            float rs = 0.0f;
#pragma unroll
            for (int j = 0; j < 4; j++) {
                s[i][j] = __expf(s[i][j] - mn);
                rs += s[i][j];
            }
            rs += __shfl_xor_sync(0xffffffffu, rs, 1);
            rs += __shfl_xor_sync(0xffffffffu, rs, 2);
            rs += __shfl_xor_sync(0xffffffffu, rs, 4);
            rs += __shfl_xor_sync(0xffffffffu, rs, 8);
            l_i[i] = l_i[i] * corr + rs;
#pragma unroll
            for (int j = 0; j < 8; j++) acc[i][j] *= corr;
            *(float4*)&Ps[(4 * ty + i) * 68 + 4 * tx] =
                make_float4(s[i][0], s[i][1], s[i][2], s[i][3]);
        }
        __syncthreads();

#pragma unroll 4
        for (int kk4 = 0; kk4 < 16; kk4++) {
            float4 p4[4];
#pragma unroll
            for (int i = 0; i < 4; i++)
                p4[i] = *(const float4*)&Ps[(4 * ty + i) * 68 + kk4 * 4];
#pragma unroll
            for (int u = 0; u < 4; u++) {
                const float* vrow = &Vs[(kk4 * 4 + u) * 128 + tx * 8];
                float4 v0 = *(const float4*)&vrow[0];
                float4 v1 = *(const float4*)&vrow[4];
                float vv[8] = {v0.x, v0.y, v0.z, v0.w, v1.x, v1.y, v1.z, v1.w};
#pragma unroll
                for (int i = 0; i < 4; i++) {
                    float p = (u == 0) ? p4[i].x : (u == 1) ? p4[i].y
                            : (u == 2) ? p4[i].z : p4[i].w;
#pragma unroll
                    for (int j = 0; j < 8; j++)
                        acc[i][j] = fmaf(p, vv[j], acc[i][j]);
                }
            }
        }
    }

    // Epilogue: divide by l, split to hi/lo bf16 for GEMM2
#pragma unroll
    for (int i = 0; i < 4; i++) {
        float inv = 1.0f / l_i[i];
        size_t off = (size_t)(b * TT + m0 + 4 * ty + i) * NE + h * 128 + tx * 8;
        float o[8];
#pragma unroll
        for (int j = 0; j < 8; j++) o[j] = acc[i][j] * inv;

        union { __nv_bfloat162 h2[4]; uint4 u; } ph, pl;
#pragma unroll
        for (int j = 0; j < 4; j++) {
            __nv_bfloat16 ha = __float2bfloat16(o[2 * j]);
            __nv_bfloat16 hb = __float2bfloat16(o[2 * j + 1]);
            __nv_bfloat16 la = __float2bfloat16(o[2 * j] - __bfloat162float(ha));
            __nv_bfloat16 lb = __float2bfloat16(o[2 * j + 1] - __bfloat162float(hb));
            ph.h2[j] = __nv_bfloat162(ha, hb);
            pl.h2[j] = __nv_bfloat162(la, lb);
        }
        *(uint4*)&g_ath[off] = ph.u;
        *(uint4*)&g_atl[off] = pl.u;
    }
}

// ---------------------------------------------------------------------------
extern "C" void kernel_launch(void* const* d_in, const int* in_sizes, int n_in,
                              void* d_out, int out_size) {
    const float* x      = (const float*)d_in[0];
    const float* w_attn = (const float*)d_in[1];
    const float* w_out  = (const float*)d_in[2];
    float* out = (float*)d_out;

    float* qkv = nullptr;
    __nv_bfloat16 *xh, *xl, *wah, *wal, *woh, *wol, *ath, *atl;
    cudaGetSymbolAddress((void**)&qkv, g_qkv);
    cudaGetSymbolAddress((void**)&xh, g_xh);
    cudaGetSymbolAddress((void**)&xl, g_xl);
    cudaGetSymbolAddress((void**)&wah, g_wah);
    cudaGetSymbolAddress((void**)&wal, g_wal);
    cudaGetSymbolAddress((void**)&woh, g_woh);
    cudaGetSymbolAddress((void**)&wol, g_wol);
    cudaGetSymbolAddress((void**)&ath, g_ath);
    cudaGetSymbolAddress((void**)&atl, g_atl);

    cudaFuncSetAttribute(mqa_flash,
                         cudaFuncAttributeMaxDynamicSharedMemorySize, FLASH_SMEM);
    cudaFuncSetAttribute(gemm_bf16x3,
                         cudaFuncAttributeMaxDynamicSharedMemorySize, GEMM_SMEM);

    // 0) split inputs into hi/lo bf16
    split_kernel<<<(MROWS * NE / 4 + 255) / 256, 256>>>(x, xh, xl, MROWS * NE / 4);
    split_kernel<<<(QKV_LD * NE / 4 + 255) / 256, 256>>>(w_attn, wah, wal, QKV_LD * NE / 4);
    split_kernel<<<(NE * NE / 4 + 255) / 256, 256>>>(w_out, woh, wol, NE * NE / 4);

    // 1) qkv = x @ w_attn^T (warp-mma split-bf16)
    gemm_bf16x3<<<dim3(QKV_LD / 128, MROWS / 128), 256, GEMM_SMEM>>>(
        xh, xl, wah, wal, qkv, QKV_LD);

    // 2) RoPE
    rope_kernel<<<MROWS, 64>>>();

    // 3) attention -> att hi/lo bf16
    mqa_flash<<<dim3(TT / 64, NH, BB), 256, FLASH_SMEM>>>();

    // 4) out = att @ w_out^T (warp-mma split-bf16)
    gemm_bf16x3<<<dim3(NE / 128, MROWS / 128), 256, GEMM_SMEM>>>(
        ath, atl, woh, wol, out, NE);
}

// round 6
// speedup vs baseline: 3.2598x; 2.4525x over previous
#include <cuda_runtime.h>
#include <cuda_bf16.h>
#include <math.h>
#include <stdint.h>

// Problem constants
#define BB      2
#define TT      2048
#define NH      16
#define HD      128
#define NE      2048
#define QKV_LD  2304
#define MROWS   (BB*TT)         // 4096
#define KDIM    2048

// Scratch (__device__ globals; no allocation allowed)
__device__ float g_qkv[(size_t)MROWS * QKV_LD];
__device__ __nv_bfloat16 g_xh[(size_t)MROWS * NE];
__device__ __nv_bfloat16 g_xl[(size_t)MROWS * NE];
__device__ __nv_bfloat16 g_wah[(size_t)QKV_LD * NE];
__device__ __nv_bfloat16 g_wal[(size_t)QKV_LD * NE];
__device__ __nv_bfloat16 g_woh[(size_t)NE * NE];
__device__ __nv_bfloat16 g_wol[(size_t)NE * NE];
__device__ __nv_bfloat16 g_ath[(size_t)MROWS * NE];
__device__ __nv_bfloat16 g_atl[(size_t)MROWS * NE];
// flash inputs (post-rope, pre-split)
__device__ __nv_bfloat16 g_qh[(size_t)MROWS * NE];   // Q pre-scaled hi
__device__ __nv_bfloat16 g_ql[(size_t)MROWS * NE];   // Q pre-scaled lo
__device__ __nv_bfloat16 g_kh[(size_t)MROWS * HD];
__device__ __nv_bfloat16 g_kl[(size_t)MROWS * HD];
__device__ __nv_bfloat16 g_vth[(size_t)BB * HD * TT];  // V^T [b][d][key]
__device__ __nv_bfloat16 g_vtl[(size_t)BB * HD * TT];

// ---------------------------------------------------------------------------
// Helpers
// ---------------------------------------------------------------------------
__device__ __forceinline__ uint32_t smem_u32(const void* p) {
    uint32_t a;
    asm("{ .reg .u64 t; cvta.to.shared.u64 t, %1; cvt.u32.u64 %0, t; }"
        : "=r"(a) : "l"(p));
    return a;
}

__device__ __forceinline__ void ldsm_x4(uint32_t& r0, uint32_t& r1,
                                        uint32_t& r2, uint32_t& r3,
                                        uint32_t addr) {
    asm volatile("ldmatrix.sync.aligned.m8n8.x4.shared.b16 {%0,%1,%2,%3}, [%4];"
                 : "=r"(r0), "=r"(r1), "=r"(r2), "=r"(r3) : "r"(addr));
}

__device__ __forceinline__ void mma_16816(float* d, const uint32_t* a,
                                          const uint32_t* b) {
    asm volatile(
        "mma.sync.aligned.m16n8k16.row.col.f32.bf16.bf16.f32 "
        "{%0,%1,%2,%3}, {%4,%5,%6,%7}, {%8,%9}, {%0,%1,%2,%3};"
        : "+f"(d[0]), "+f"(d[1]), "+f"(d[2]), "+f"(d[3])
        : "r"(a[0]), "r"(a[1]), "r"(a[2]), "r"(a[3]), "r"(b[0]), "r"(b[1]));
}

#define CP_ASYNC16(dst, src) \
    asm volatile("cp.async.cg.shared.global [%0], [%1], 16;" :: "r"(dst), "l"(src))

// split (a,b) -> hi bf16x2 and lo bf16x2 packed as u32 (low half = a)
__device__ __forceinline__ void split2(float a, float b, uint32_t& h, uint32_t& l) {
    __nv_bfloat16 ha = __float2bfloat16(a), hb = __float2bfloat16(b);
    float ra = a - __bfloat162float(ha);
    float rb = b - __bfloat162float(hb);
    __nv_bfloat162 hv(ha, hb);
    __nv_bfloat162 lv(__float2bfloat16(ra), __float2bfloat16(rb));
    h = *(uint32_t*)&hv;
    l = *(uint32_t*)&lv;
}

// ---------------------------------------------------------------------------
// Split fp32 -> (hi, lo) bf16 (x, w_attn, w_out)
// ---------------------------------------------------------------------------
__global__ __launch_bounds__(256) void split_kernel(const float* __restrict__ src,
                                                    __nv_bfloat16* __restrict__ hi,
                                                    __nv_bfloat16* __restrict__ lo,
                                                    int n4) {
    int i = blockIdx.x * 256 + threadIdx.x;
    if (i >= n4) return;
    float4 v = ((const float4*)src)[i];
    uint32_t h0, l0, h1, l1;
    split2(v.x, v.y, h0, l0);
    split2(v.z, v.w, h1, l1);
    ((uint2*)hi)[i] = make_uint2(h0, h1);
    ((uint2*)lo)[i] = make_uint2(l0, l1);
}

// ---------------------------------------------------------------------------
// Warp-mma split-bf16 GEMM (verified round 5)
// ---------------------------------------------------------------------------
#define GKT 64
#define GNT (KDIM / GKT)
#define ROWB 144
#define TILE_B (128 * ROWB)
#define STAGE_B (4 * TILE_B)
#define GEMM_SMEM (2 * STAGE_B)

__global__ __launch_bounds__(256, 1) void gemm_bf16x3(
    const __nv_bfloat16* __restrict__ Ah, const __nv_bfloat16* __restrict__ Al,
    const __nv_bfloat16* __restrict__ Bh, const __nv_bfloat16* __restrict__ Bl,
    float* __restrict__ C, int ldc) {
    extern __shared__ char dynsmem[];
    const uint32_t sbase0 = smem_u32(dynsmem);

    const int tid = threadIdx.x;
    const int lane = tid & 31;
    const int warp = tid >> 5;
    const int wm = warp & 3;
    const int wn = warp >> 2;
    const int m0 = blockIdx.y * 128;
    const int n0 = blockIdx.x * 128;

    const __nv_bfloat16* srcs[4] = {
        Ah + (size_t)m0 * KDIM, Al + (size_t)m0 * KDIM,
        Bh + (size_t)n0 * KDIM, Bl + (size_t)n0 * KDIM};

    auto load_stage = [&](int s, int kt) {
#pragma unroll
        for (int i = 0; i < 16; i++) {
            const int t = i >> 2;
            const int f = (i & 3) * 256 + tid;
            const int r = f >> 3;
            const int c = f & 7;
            const __nv_bfloat16* g = srcs[t] + (size_t)r * KDIM + kt * GKT + c * 8;
            uint32_t d = sbase0 + s * STAGE_B + t * TILE_B + r * ROWB + c * 16;
            CP_ASYNC16(d, g);
        }
        asm volatile("cp.async.commit_group;" ::: "memory");
    };

    float acc[16][4];
#pragma unroll
    for (int t = 0; t < 16; t++)
#pragma unroll
        for (int j = 0; j < 4; j++) acc[t][j] = 0.0f;

    load_stage(0, 0);

    for (int kt = 0; kt < GNT; kt++) {
        const int s = kt & 1;
        if (kt + 1 < GNT) {
            load_stage((kt + 1) & 1, kt + 1);
            asm volatile("cp.async.wait_group 1;" ::: "memory");
        } else {
            asm volatile("cp.async.wait_group 0;" ::: "memory");
        }
        __syncthreads();

        const uint32_t st = sbase0 + s * STAGE_B;
        const uint32_t aBh = st + (wm * 32) * ROWB;
        const uint32_t aBl = aBh + TILE_B;
        const uint32_t bBh = st + 2 * TILE_B + (wn * 64) * ROWB;
        const uint32_t bBl = bBh + TILE_B;

#pragma unroll
        for (int ks = 0; ks < 4; ks++) {
            const uint32_t kc = ks * 32 + (lane >> 4) * 16;
            uint32_t ah[2][4], al[2][4];
#pragma unroll
            for (int mi = 0; mi < 2; mi++) {
                uint32_t ao = (mi * 16 + (lane & 15)) * ROWB + kc;
                ldsm_x4(ah[mi][0], ah[mi][1], ah[mi][2], ah[mi][3], aBh + ao);
                ldsm_x4(al[mi][0], al[mi][1], al[mi][2], al[mi][3], aBl + ao);
            }
            const int mat = lane >> 3;
            const uint32_t bo = ((mat >> 1) * 8 + (lane & 7)) * ROWB
                              + ks * 32 + (mat & 1) * 16;
            uint32_t bh[8][2], bl[8][2];
#pragma unroll
            for (int g = 0; g < 4; g++) {
                uint32_t o = g * 16 * ROWB + bo;
                ldsm_x4(bh[2 * g][0], bh[2 * g][1], bh[2 * g + 1][0],
                        bh[2 * g + 1][1], bBh + o);
                ldsm_x4(bl[2 * g][0], bl[2 * g][1], bl[2 * g + 1][0],
                        bl[2 * g + 1][1], bBl + o);
            }
#pragma unroll
            for (int mi = 0; mi < 2; mi++)
#pragma unroll
                for (int nj = 0; nj < 8; nj++) {
                    mma_16816(acc[mi * 8 + nj], ah[mi], bh[nj]);
                    mma_16816(acc[mi * 8 + nj], ah[mi], bl[nj]);
                    mma_16816(acc[mi * 8 + nj], al[mi], bh[nj]);
                }
        }
        __syncthreads();
    }

    const int rbase = m0 + wm * 32 + (lane >> 2);
    const int cbase = n0 + wn * 64 + (lane & 3) * 2;
#pragma unroll
    for (int mi = 0; mi < 2; mi++)
#pragma unroll
        for (int nj = 0; nj < 8; nj++) {
            float* c0 = C + (size_t)(rbase + mi * 16) * ldc + cbase + nj * 8;
            float* c1 = c0 + 8 * ldc;
            *(float2*)c0 = make_float2(acc[mi * 8 + nj][0], acc[mi * 8 + nj][1]);
            *(float2*)c1 = make_float2(acc[mi * 8 + nj][2], acc[mi * 8 + nj][3]);
        }
}

// ---------------------------------------------------------------------------
// RoPE (verified): pos[j] = 10000 ** (-(4j+1)/128)
// ---------------------------------------------------------------------------
__global__ __launch_bounds__(64) void rope_kernel() {
    const int row = blockIdx.x;
    const int t = row & (TT - 1);
    const int j = threadIdx.x;

    double e = ((-4.0 * (double)j - 1.0) / 128.0) * 9.210340371976184;
    float freq = (float)exp(e);
    float ang = (float)t * freq;
    float c = cosf(ang);
    float s = sinf(ang);

    float* base = g_qkv + (size_t)row * QKV_LD;
#pragma unroll
    for (int seg = 0; seg < 17; seg++) {
        float* p = base + seg * 128;
        float x1 = p[j];
        float x2 = p[j + 64];
        p[j]      = x1 * c - x2 * s;
        p[j + 64] = x2 * c + x1 * s;
    }
}

// ---------------------------------------------------------------------------
// Post-rope split: Q (pre-scaled 1/sqrt(d)) and K -> hi/lo bf16
// ---------------------------------------------------------------------------
__global__ __launch_bounds__(256) void qk_split() {
    const int row = blockIdx.x;
    const int tid = threadIdx.x;
    const float* src = g_qkv + (size_t)row * QKV_LD;
    const float scale = 0.08838834764831845f;

#pragma unroll
    for (int i = 0; i < 2; i++) {
        int f = i * 256 + tid;                       // float4 index 0..511
        float4 v = *(const float4*)&src[f * 4];
        uint32_t h0, l0, h1, l1;
        split2(v.x * scale, v.y * scale, h0, l0);
        split2(v.z * scale, v.w * scale, h1, l1);
        *(uint2*)&g_qh[(size_t)row * NE + f * 4] = make_uint2(h0, h1);
        *(uint2*)&g_ql[(size_t)row * NE + f * 4] = make_uint2(l0, l1);
    }
    if (tid < 32) {
        float4 v = *(const float4*)&src[2048 + tid * 4];
        uint32_t h0, l0, h1, l1;
        split2(v.x, v.y, h0, l0);
        split2(v.z, v.w, h1, l1);
        *(uint2*)&g_kh[(size_t)row * HD + tid * 4] = make_uint2(h0, h1);
        *(uint2*)&g_kl[(size_t)row * HD + tid * 4] = make_uint2(l0, l1);
    }
}

// ---------------------------------------------------------------------------
// V transpose + split: g_qkv v-part [key][d] fp32 -> g_vth/g_vtl [b][d][key]
// ---------------------------------------------------------------------------
__global__ __launch_bounds__(256) void v_split_t() {
    const int blk = blockIdx.x;
    const int b = blk >> 5;                 // TT/64 = 32 blocks per batch
    const int t0 = (blk & 31) * 64;
    __shared__ float sv[64][132];
    const int tid = threadIdx.x;

#pragma unroll
    for (int i = 0; i < 8; i++) {
        int f = i * 256 + tid;
        int r = f >> 5;
        int c4 = (f & 31) * 4;
        float4 v = *(const float4*)
            &g_qkv[(size_t)(b * TT + t0 + r) * QKV_LD + 2176 + c4];
        sv[r][c4 + 0] = v.x; sv[r][c4 + 1] = v.y;
        sv[r][c4 + 2] = v.z; sv[r][c4 + 3] = v.w;
    }
    __syncthreads();

    const int d = tid >> 1;
    const int half = tid & 1;
    size_t orow = ((size_t)b * HD + d) * TT + t0 + half * 32;
#pragma unroll
    for (int j = 0; j < 4; j++) {
        uint32_t hw[4], lw[4];
#pragma unroll
        for (int u = 0; u < 4; u++) {
            int k0 = half * 32 + j * 8 + u * 2;
            split2(sv[k0][d], sv[k0 + 1][d], hw[u], lw[u]);
        }
        *(uint4*)&g_vth[orow + j * 8] = make_uint4(hw[0], hw[1], hw[2], hw[3]);
        *(uint4*)&g_vtl[orow + j * 8] = make_uint4(lw[0], lw[1], lw[2], lw[3]);
    }
}

// ---------------------------------------------------------------------------
// MMA flash MQA: CTA = (b, h, 128 q rows); 8 warps x 16-row bands.
// 64-key chunks x 32, double-buffered cp.async.
// S = QhKh + QhKl + QlKh ; P split in-register ; O += PhVh + PlVh + PhVl
// ---------------------------------------------------------------------------
#define CKEYS 64
#define NCH (TT / CKEYS)                 // 32
#define QROWB 272
#define KROWB 272
#define VROWB 144
#define QTILE_B (128 * QROWB)            // 34816
#define KTILE_B (CKEYS * KROWB)          // 17408
#define VTILE_B (HD * VROWB)             // 18432
#define FSTAGE_B (2 * KTILE_B + 2 * VTILE_B)     // 71680
#define FLASH_SMEM (2 * QTILE_B + 2 * FSTAGE_B)  // 212992

__global__ __launch_bounds__(256, 1) void mqa_flash_mma() {
    extern __shared__ char fsm[];
    const uint32_t sb = smem_u32(fsm);
    const int tid = threadIdx.x;
    const int lane = tid & 31;
    const int warp = tid >> 5;
    const int b = blockIdx.z;
    const int h = blockIdx.y;
    const int m0 = blockIdx.x * 128;

    // ---- load Q hi/lo into smem (row-major, stride QROWB) ----
    {
        const __nv_bfloat16* gq = g_qh + (size_t)(b * TT + m0) * NE + h * 128;
        const __nv_bfloat16* gl = g_ql + (size_t)(b * TT + m0) * NE + h * 128;
#pragma unroll
        for (int i = 0; i < 8; i++) {
            int f = i * 256 + tid;
            int r = f >> 4;
            int c = f & 15;
            uint4 vh = *(const uint4*)(gq + (size_t)r * NE + c * 8);
            uint4 vl = *(const uint4*)(gl + (size_t)r * NE + c * 8);
            *(uint4*)(fsm + r * QROWB + c * 16) = vh;
            *(uint4*)(fsm + QTILE_B + r * QROWB + c * 16) = vl;
        }
    }

    auto load_stage = [&](int s, int kb) {
        uint32_t st = sb + 2 * QTILE_B + s * FSTAGE_B;
        const __nv_bfloat16* kh = g_kh + (size_t)(b * TT + kb * CKEYS) * HD;
        const __nv_bfloat16* kl = g_kl + (size_t)(b * TT + kb * CKEYS) * HD;
#pragma unroll
        for (int i = 0; i < 4; i++) {
            int f = i * 256 + tid;
            int r = f >> 4;                 // 0..63
            int c = f & 15;
            CP_ASYNC16(st + r * KROWB + c * 16, kh + (size_t)r * HD + c * 8);
            CP_ASYNC16(st + KTILE_B + r * KROWB + c * 16, kl + (size_t)r * HD + c * 8);
        }
        const __nv_bfloat16* vh = g_vth + (size_t)b * HD * TT + kb * CKEYS;
        const __nv_bfloat16* vl = g_vtl + (size_t)b * HD * TT + kb * CKEYS;
#pragma unroll
        for (int i = 0; i < 4; i++) {
            int f = i * 256 + tid;
            int r = f >> 3;                 // 0..127
            int c = f & 7;
            CP_ASYNC16(st + 2 * KTILE_B + r * VROWB + c * 16,
                       vh + (size_t)r * TT + c * 8);
            CP_ASYNC16(st + 2 * KTILE_B + VTILE_B + r * VROWB + c * 16,
                       vl + (size_t)r * TT + c * 8);
        }
        asm volatile("cp.async.commit_group;" ::: "memory");
    };

    float oacc[16][4];
#pragma unroll
    for (int t = 0; t < 16; t++)
#pragma unroll
        for (int j = 0; j < 4; j++) oacc[t][j] = 0.0f;
    float m_i[2] = {-INFINITY, -INFINITY};
    float l_i[2] = {0.0f, 0.0f};

    load_stage(0, 0);

    for (int kb = 0; kb < NCH; kb++) {
        const int s = kb & 1;
        if (kb + 1 < NCH) {
            load_stage((kb + 1) & 1, kb + 1);
            asm volatile("cp.async.wait_group 1;" ::: "memory");
        } else {
            asm volatile("cp.async.wait_group 0;" ::: "memory");
        }
        __syncthreads();

        const uint32_t st = sb + 2 * QTILE_B + s * FSTAGE_B;
        const int mat = lane >> 3;

        // ---- S = Q @ K^T (3-term) ----
        float sfr[8][4];
#pragma unroll
        for (int t = 0; t < 8; t++)
#pragma unroll
            for (int j = 0; j < 4; j++) sfr[t][j] = 0.0f;

#pragma unroll
        for (int ks = 0; ks < 8; ks++) {
            uint32_t ao = (warp * 16 + (lane & 15)) * QROWB
                        + ks * 32 + (lane >> 4) * 16;
            uint32_t ah[4], al[4];
            ldsm_x4(ah[0], ah[1], ah[2], ah[3], sb + ao);
            ldsm_x4(al[0], al[1], al[2], al[3], sb + QTILE_B + ao);

            uint32_t bo = ((mat >> 1) * 8 + (lane & 7)) * KROWB
                        + ks * 32 + (mat & 1) * 16;
            uint32_t bh[8][2], bl[8][2];
#pragma unroll
            for (int g = 0; g < 4; g++) {
                uint32_t o = g * 16 * KROWB + bo;
                ldsm_x4(bh[2 * g][0], bh[2 * g][1], bh[2 * g + 1][0],
                        bh[2 * g + 1][1], st + o);
                ldsm_x4(bl[2 * g][0], bl[2 * g][1], bl[2 * g + 1][0],
                        bl[2 * g + 1][1], st + KTILE_B + o);
            }
#pragma unroll
            for (int nj = 0; nj < 8; nj++) {
                mma_16816(sfr[nj], ah, bh[nj]);
                mma_16816(sfr[nj], ah, bl[nj]);
                mma_16816(sfr[nj], al, bh[nj]);
            }
        }

        // ---- online softmax (rows r0=lane>>2, r1=r0+8 within band) ----
#pragma unroll
        for (int half = 0; half < 2; half++) {
            float mx = -INFINITY;
#pragma unroll
            for (int nj = 0; nj < 8; nj++)
                mx = fmaxf(mx, fmaxf(sfr[nj][2 * half], sfr[nj][2 * half + 1]));
            mx = fmaxf(mx, __shfl_xor_sync(0xffffffffu, mx, 1));
            mx = fmaxf(mx, __shfl_xor_sync(0xffffffffu, mx, 2));
            float mn = fmaxf(m_i[half], mx);
            float corr = __expf(m_i[half] - mn);
            m_i[half] = mn;
            float sum = 0.0f;
#pragma unroll
            for (int nj = 0; nj < 8; nj++) {
                float p0 = __expf(sfr[nj][2 * half] - mn);
                float p1 = __expf(sfr[nj][2 * half + 1] - mn);
                sfr[nj][2 * half] = p0;
                sfr[nj][2 * half + 1] = p1;
                sum += p0 + p1;
            }
            sum += __shfl_xor_sync(0xffffffffu, sum, 1);
            sum += __shfl_xor_sync(0xffffffffu, sum, 2);
            l_i[half] = l_i[half] * corr + sum;
#pragma unroll
            for (int nt = 0; nt < 16; nt++) {
                oacc[nt][2 * half] *= corr;
                oacc[nt][2 * half + 1] *= corr;
            }
        }

        // ---- O += P @ V (3-term, P split in-register) ----
        const uint32_t vbh = st + 2 * KTILE_B;
        const uint32_t vbl = vbh + VTILE_B;
#pragma unroll
        for (int kk = 0; kk < 4; kk++) {
            uint32_t ph[4], pl[4];
            split2(sfr[2 * kk][0], sfr[2 * kk][1], ph[0], pl[0]);
            split2(sfr[2 * kk][2], sfr[2 * kk][3], ph[1], pl[1]);
            split2(sfr[2 * kk + 1][0], sfr[2 * kk + 1][1], ph[2], pl[2]);
            split2(sfr[2 * kk + 1][2], sfr[2 * kk + 1][3], ph[3], pl[3]);

            uint32_t bo = ((mat >> 1) * 8 + (lane & 7)) * VROWB
                        + kk * 32 + (mat & 1) * 16;
#pragma unroll
            for (int g = 0; g < 8; g++) {
                uint32_t o = g * 16 * VROWB + bo;
                uint32_t vh0[2], vh1[2], vl0[2], vl1[2];
                ldsm_x4(vh0[0], vh0[1], vh1[0], vh1[1], vbh + o);
                ldsm_x4(vl0[0], vl0[1], vl1[0], vl1[1], vbl + o);
                mma_16816(oacc[2 * g], ph, vh0);
                mma_16816(oacc[2 * g], pl, vh0);
                mma_16816(oacc[2 * g], ph, vl0);
                mma_16816(oacc[2 * g + 1], ph, vh1);
                mma_16816(oacc[2 * g + 1], pl, vh1);
                mma_16816(oacc[2 * g + 1], ph, vl1);
            }
        }
        __syncthreads();
    }

    // ---- epilogue: O/l -> hi/lo bf16 att ----
#pragma unroll
    for (int half = 0; half < 2; half++) {
        const int row = m0 + warp * 16 + (lane >> 2) + half * 8;
        const float inv = 1.0f / l_i[half];
        size_t off = (size_t)(b * TT + row) * NE + h * 128 + (lane & 3) * 2;
#pragma unroll
        for (int nt = 0; nt < 16; nt++) {
            uint32_t hw, lw;
            split2(oacc[nt][2 * half] * inv, oacc[nt][2 * half + 1] * inv, hw, lw);
            *(uint32_t*)&g_ath[off + nt * 8] = hw;
            *(uint32_t*)&g_atl[off + nt * 8] = lw;
        }
    }
}

// ---------------------------------------------------------------------------
extern "C" void kernel_launch(void* const* d_in, const int* in_sizes, int n_in,
                              void* d_out, int out_size) {
    const float* x      = (const float*)d_in[0];
    const float* w_attn = (const float*)d_in[1];
    const float* w_out  = (const float*)d_in[2];
    float* out = (float*)d_out;

    float* qkv = nullptr;
    __nv_bfloat16 *xh, *xl, *wah, *wal, *woh, *wol, *ath, *atl;
    cudaGetSymbolAddress((void**)&qkv, g_qkv);
    cudaGetSymbolAddress((void**)&xh, g_xh);
    cudaGetSymbolAddress((void**)&xl, g_xl);
    cudaGetSymbolAddress((void**)&wah, g_wah);
    cudaGetSymbolAddress((void**)&wal, g_wal);
    cudaGetSymbolAddress((void**)&woh, g_woh);
    cudaGetSymbolAddress((void**)&wol, g_wol);
    cudaGetSymbolAddress((void**)&ath, g_ath);
    cudaGetSymbolAddress((void**)&atl, g_atl);

    cudaFuncSetAttribute(gemm_bf16x3,
                         cudaFuncAttributeMaxDynamicSharedMemorySize, GEMM_SMEM);
    cudaFuncSetAttribute(mqa_flash_mma,
                         cudaFuncAttributeMaxDynamicSharedMemorySize, FLASH_SMEM);

    // 0) split inputs
    split_kernel<<<(MROWS * NE / 4 + 255) / 256, 256>>>(x, xh, xl, MROWS * NE / 4);
    split_kernel<<<(QKV_LD * NE / 4 + 255) / 256, 256>>>(w_attn, wah, wal, QKV_LD * NE / 4);
    split_kernel<<<(NE * NE / 4 + 255) / 256, 256>>>(w_out, woh, wol, NE * NE / 4);

    // 1) qkv = x @ w_attn^T
    gemm_bf16x3<<<dim3(QKV_LD / 128, MROWS / 128), 256, GEMM_SMEM>>>(
        xh, xl, wah, wal, qkv, QKV_LD);

    // 2) RoPE (in place, fp32)
    rope_kernel<<<MROWS, 64>>>();

    // 3) split post-rope Q/K, transpose+split V
    qk_split<<<MROWS, 256>>>();
    v_split_t<<<BB * (TT / 64), 256>>>();

    // 4) attention (mma) -> att hi/lo bf16
    mqa_flash_mma<<<dim3(TT / 128, NH, BB), 256, FLASH_SMEM>>>();

    // 5) out = att @ w_out^T
    gemm_bf16x3<<<dim3(NE / 128, MROWS / 128), 256, GEMM_SMEM>>>(
        ath, atl, woh, wol, out, NE);
}

// round 7
// speedup vs baseline: 3.2699x; 1.0031x over previous
#include <cuda_runtime.h>
#include <cuda_bf16.h>
#include <math.h>
#include <stdint.h>

// Problem constants
#define BB      2
#define TT      2048
#define NH      16
#define HD      128
#define NE      2048
#define QKV_LD  2304
#define MROWS   (BB*TT)         // 4096
#define KDIM    2048

// Scratch (__device__ globals; no allocation allowed)
__device__ float g_qkv[(size_t)MROWS * QKV_LD];
__device__ __nv_bfloat16 g_xh[(size_t)MROWS * NE];
__device__ __nv_bfloat16 g_xl[(size_t)MROWS * NE];
__device__ __nv_bfloat16 g_wah[(size_t)QKV_LD * NE];
__device__ __nv_bfloat16 g_wal[(size_t)QKV_LD * NE];
__device__ __nv_bfloat16 g_woh[(size_t)NE * NE];
__device__ __nv_bfloat16 g_wol[(size_t)NE * NE];
__device__ __nv_bfloat16 g_ath[(size_t)MROWS * NE];
__device__ __nv_bfloat16 g_atl[(size_t)MROWS * NE];
// flash inputs (post-rope, pre-split)
__device__ __nv_bfloat16 g_qh[(size_t)MROWS * NE];   // Q pre-scaled hi
__device__ __nv_bfloat16 g_ql[(size_t)MROWS * NE];   // Q pre-scaled lo
__device__ __nv_bfloat16 g_kh[(size_t)MROWS * HD];
__device__ __nv_bfloat16 g_kl[(size_t)MROWS * HD];
__device__ __nv_bfloat16 g_vth[(size_t)BB * HD * TT];  // V^T [b][d][key]
__device__ __nv_bfloat16 g_vtl[(size_t)BB * HD * TT];

// ---------------------------------------------------------------------------
// Helpers
// ---------------------------------------------------------------------------
__device__ __forceinline__ uint32_t smem_u32(const void* p) {
    uint32_t a;
    asm("{ .reg .u64 t; cvta.to.shared.u64 t, %1; cvt.u32.u64 %0, t; }"
        : "=r"(a) : "l"(p));
    return a;
}

__device__ __forceinline__ void ldsm_x4(uint32_t& r0, uint32_t& r1,
                                        uint32_t& r2, uint32_t& r3,
                                        uint32_t addr) {
    asm volatile("ldmatrix.sync.aligned.m8n8.x4.shared.b16 {%0,%1,%2,%3}, [%4];"
                 : "=r"(r0), "=r"(r1), "=r"(r2), "=r"(r3) : "r"(addr));
}

__device__ __forceinline__ void mma_16816(float* d, const uint32_t* a,
                                          const uint32_t* b) {
    asm volatile(
        "mma.sync.aligned.m16n8k16.row.col.f32.bf16.bf16.f32 "
        "{%0,%1,%2,%3}, {%4,%5,%6,%7}, {%8,%9}, {%0,%1,%2,%3};"
        : "+f"(d[0]), "+f"(d[1]), "+f"(d[2]), "+f"(d[3])
        : "r"(a[0]), "r"(a[1]), "r"(a[2]), "r"(a[3]), "r"(b[0]), "r"(b[1]));
}

#define CP_ASYNC16(dst, src) \
    asm volatile("cp.async.cg.shared.global [%0], [%1], 16;" :: "r"(dst), "l"(src))

// split (a,b) -> hi bf16x2 and lo bf16x2 packed as u32 (low half = a)
__device__ __forceinline__ void split2(float a, float b, uint32_t& h, uint32_t& l) {
    __nv_bfloat16 ha = __float2bfloat16(a), hb = __float2bfloat16(b);
    float ra = a - __bfloat162float(ha);
    float rb = b - __bfloat162float(hb);
    __nv_bfloat162 hv(ha, hb);
    __nv_bfloat162 lv(__float2bfloat16(ra), __float2bfloat16(rb));
    h = *(uint32_t*)&hv;
    l = *(uint32_t*)&lv;
}

// ---------------------------------------------------------------------------
// Split fp32 -> (hi, lo) bf16 (x, w_attn, w_out)
// ---------------------------------------------------------------------------
__global__ __launch_bounds__(256) void split_kernel(const float* __restrict__ src,
                                                    __nv_bfloat16* __restrict__ hi,
                                                    __nv_bfloat16* __restrict__ lo,
                                                    int n4) {
    int i = blockIdx.x * 256 + threadIdx.x;
    if (i >= n4) return;
    float4 v = ((const float4*)src)[i];
    uint32_t h0, l0, h1, l1;
    split2(v.x, v.y, h0, l0);
    split2(v.z, v.w, h1, l1);
    ((uint2*)hi)[i] = make_uint2(h0, h1);
    ((uint2*)lo)[i] = make_uint2(l0, l1);
}

// ---------------------------------------------------------------------------
// Warp-mma split-bf16 GEMM with register-level fragment double buffering.
// C[M,N] = (Ah+Al)[M,K] @ (Bh+Bl)[N,K]^T, C = Ah*Bh + Ah*Bl + Al*Bh.
// CTA tile 128x128, K-tile 64, 2-stage cp.async, 8 warps (4M x 2N).
// ---------------------------------------------------------------------------
#define GKT 64
#define GNT (KDIM / GKT)
#define ROWB 144
#define TILE_B (128 * ROWB)
#define STAGE_B (4 * TILE_B)
#define GEMM_SMEM (2 * STAGE_B)

__global__ __launch_bounds__(256, 1) void gemm_bf16x3(
    const __nv_bfloat16* __restrict__ Ah, const __nv_bfloat16* __restrict__ Al,
    const __nv_bfloat16* __restrict__ Bh, const __nv_bfloat16* __restrict__ Bl,
    float* __restrict__ C, int ldc) {
    extern __shared__ char dynsmem[];
    const uint32_t sbase0 = smem_u32(dynsmem);

    const int tid = threadIdx.x;
    const int lane = tid & 31;
    const int warp = tid >> 5;
    const int wm = warp & 3;
    const int wn = warp >> 2;
    const int m0 = blockIdx.y * 128;
    const int n0 = blockIdx.x * 128;

    const __nv_bfloat16* srcs[4] = {
        Ah + (size_t)m0 * KDIM, Al + (size_t)m0 * KDIM,
        Bh + (size_t)n0 * KDIM, Bl + (size_t)n0 * KDIM};

    auto load_stage = [&](int s, int kt) {
#pragma unroll
        for (int i = 0; i < 16; i++) {
            const int t = i >> 2;
            const int f = (i & 3) * 256 + tid;
            const int r = f >> 3;
            const int c = f & 7;
            const __nv_bfloat16* g = srcs[t] + (size_t)r * KDIM + kt * GKT + c * 8;
            uint32_t d = sbase0 + s * STAGE_B + t * TILE_B + r * ROWB + c * 16;
            CP_ASYNC16(d, g);
        }
        asm volatile("cp.async.commit_group;" ::: "memory");
    };

    float acc[16][4];
#pragma unroll
    for (int t = 0; t < 16; t++)
#pragma unroll
        for (int j = 0; j < 4; j++) acc[t][j] = 0.0f;

    // fragment double buffers
    uint32_t fah[2][2][4], fal[2][2][4], fbh[2][8][2], fbl[2][8][2];
    const int mat = lane >> 3;

    load_stage(0, 0);

    for (int kt = 0; kt < GNT; kt++) {
        const int s = kt & 1;
        if (kt + 1 < GNT) {
            load_stage((kt + 1) & 1, kt + 1);
            asm volatile("cp.async.wait_group 1;" ::: "memory");
        } else {
            asm volatile("cp.async.wait_group 0;" ::: "memory");
        }
        __syncthreads();

        const uint32_t st = sbase0 + s * STAGE_B;
        const uint32_t aBh = st + (wm * 32) * ROWB;
        const uint32_t aBl = aBh + TILE_B;
        const uint32_t bBh = st + 2 * TILE_B + (wn * 64) * ROWB;
        const uint32_t bBl = bBh + TILE_B;

        auto load_frags = [&](int ks, int bf) {
            const uint32_t kc = ks * 32 + (lane >> 4) * 16;
#pragma unroll
            for (int mi = 0; mi < 2; mi++) {
                uint32_t ao = (mi * 16 + (lane & 15)) * ROWB + kc;
                ldsm_x4(fah[bf][mi][0], fah[bf][mi][1], fah[bf][mi][2],
                        fah[bf][mi][3], aBh + ao);
                ldsm_x4(fal[bf][mi][0], fal[bf][mi][1], fal[bf][mi][2],
                        fal[bf][mi][3], aBl + ao);
            }
            const uint32_t bo = ((mat >> 1) * 8 + (lane & 7)) * ROWB
                              + ks * 32 + (mat & 1) * 16;
#pragma unroll
            for (int g = 0; g < 4; g++) {
                uint32_t o = g * 16 * ROWB + bo;
                ldsm_x4(fbh[bf][2 * g][0], fbh[bf][2 * g][1],
                        fbh[bf][2 * g + 1][0], fbh[bf][2 * g + 1][1], bBh + o);
                ldsm_x4(fbl[bf][2 * g][0], fbl[bf][2 * g][1],
                        fbl[bf][2 * g + 1][0], fbl[bf][2 * g + 1][1], bBl + o);
            }
        };

        load_frags(0, 0);
#pragma unroll
        for (int ks = 0; ks < 4; ks++) {
            if (ks < 3) load_frags(ks + 1, (ks + 1) & 1);
            const int bf = ks & 1;
#pragma unroll
            for (int mi = 0; mi < 2; mi++)
#pragma unroll
                for (int nj = 0; nj < 8; nj++) {
                    mma_16816(acc[mi * 8 + nj], fah[bf][mi], fbh[bf][nj]);
                    mma_16816(acc[mi * 8 + nj], fah[bf][mi], fbl[bf][nj]);
                    mma_16816(acc[mi * 8 + nj], fal[bf][mi], fbh[bf][nj]);
                }
        }
        __syncthreads();
    }

    const int rbase = m0 + wm * 32 + (lane >> 2);
    const int cbase = n0 + wn * 64 + (lane & 3) * 2;
#pragma unroll
    for (int mi = 0; mi < 2; mi++)
#pragma unroll
        for (int nj = 0; nj < 8; nj++) {
            float* c0 = C + (size_t)(rbase + mi * 16) * ldc + cbase + nj * 8;
            float* c1 = c0 + 8 * ldc;
            *(float2*)c0 = make_float2(acc[mi * 8 + nj][0], acc[mi * 8 + nj][1]);
            *(float2*)c1 = make_float2(acc[mi * 8 + nj][2], acc[mi * 8 + nj][3]);
        }
}

// ---------------------------------------------------------------------------
// Fused RoPE + Q/K hi-lo split. Reads fp32 qkv, writes ONLY bf16 outputs
// (rotated fp32 is never needed again). Q pre-scaled by 1/sqrt(d).
// pos[j] = 10000 ** (-(4j+1)/128)  (verified round 3)
// ---------------------------------------------------------------------------
__global__ __launch_bounds__(64) void rope_split_kernel() {
    const int row = blockIdx.x;
    const int t = row & (TT - 1);
    const int j = threadIdx.x;
    const float scale = 0.08838834764831845f;

    double e = ((-4.0 * (double)j - 1.0) / 128.0) * 9.210340371976184;
    float freq = (float)exp(e);
    float ang = (float)t * freq;
    float c = cosf(ang);
    float s = sinf(ang);

    const float* base = g_qkv + (size_t)row * QKV_LD;
#pragma unroll
    for (int seg = 0; seg < 17; seg++) {
        const float* p = base + seg * 128;
        float x1 = p[j];
        float x2 = p[j + 64];
        float r1 = x1 * c - x2 * s;
        float r2 = x2 * c + x1 * s;
        if (seg < 16) {
            r1 *= scale; r2 *= scale;
            __nv_bfloat16 h1 = __float2bfloat16(r1);
            __nv_bfloat16 h2 = __float2bfloat16(r2);
            size_t o = (size_t)row * NE + seg * 128 + j;
            g_qh[o]      = h1;
            g_qh[o + 64] = h2;
            g_ql[o]      = __float2bfloat16(r1 - __bfloat162float(h1));
            g_ql[o + 64] = __float2bfloat16(r2 - __bfloat162float(h2));
        } else {
            __nv_bfloat16 h1 = __float2bfloat16(r1);
            __nv_bfloat16 h2 = __float2bfloat16(r2);
            size_t o = (size_t)row * HD + j;
            g_kh[o]      = h1;
            g_kh[o + 64] = h2;
            g_kl[o]      = __float2bfloat16(r1 - __bfloat162float(h1));
            g_kl[o + 64] = __float2bfloat16(r2 - __bfloat162float(h2));
        }
    }
}

// ---------------------------------------------------------------------------
// V transpose + split: g_qkv v-part [key][d] fp32 -> g_vth/g_vtl [b][d][key]
// ---------------------------------------------------------------------------
__global__ __launch_bounds__(256) void v_split_t() {
    const int blk = blockIdx.x;
    const int b = blk >> 5;
    const int t0 = (blk & 31) * 64;
    __shared__ float sv[64][132];
    const int tid = threadIdx.x;

#pragma unroll
    for (int i = 0; i < 8; i++) {
        int f = i * 256 + tid;
        int r = f >> 5;
        int c4 = (f & 31) * 4;
        float4 v = *(const float4*)
            &g_qkv[(size_t)(b * TT + t0 + r) * QKV_LD + 2176 + c4];
        sv[r][c4 + 0] = v.x; sv[r][c4 + 1] = v.y;
        sv[r][c4 + 2] = v.z; sv[r][c4 + 3] = v.w;
    }
    __syncthreads();

    const int d = tid >> 1;
    const int half = tid & 1;
    size_t orow = ((size_t)b * HD + d) * TT + t0 + half * 32;
#pragma unroll
    for (int j = 0; j < 4; j++) {
        uint32_t hw[4], lw[4];
#pragma unroll
        for (int u = 0; u < 4; u++) {
            int k0 = half * 32 + j * 8 + u * 2;
            split2(sv[k0][d], sv[k0 + 1][d], hw[u], lw[u]);
        }
        *(uint4*)&g_vth[orow + j * 8] = make_uint4(hw[0], hw[1], hw[2], hw[3]);
        *(uint4*)&g_vtl[orow + j * 8] = make_uint4(lw[0], lw[1], lw[2], lw[3]);
    }
}

// ---------------------------------------------------------------------------
// MMA flash MQA (verified round 6)
// ---------------------------------------------------------------------------
#define CKEYS 64
#define NCH (TT / CKEYS)
#define QROWB 272
#define KROWB 272
#define VROWB 144
#define QTILE_B (128 * QROWB)
#define KTILE_B (CKEYS * KROWB)
#define VTILE_B (HD * VROWB)
#define FSTAGE_B (2 * KTILE_B + 2 * VTILE_B)
#define FLASH_SMEM (2 * QTILE_B + 2 * FSTAGE_B)

__global__ __launch_bounds__(256, 1) void mqa_flash_mma() {
    extern __shared__ char fsm[];
    const uint32_t sb = smem_u32(fsm);
    const int tid = threadIdx.x;
    const int lane = tid & 31;
    const int warp = tid >> 5;
    const int b = blockIdx.z;
    const int h = blockIdx.y;
    const int m0 = blockIdx.x * 128;

    {
        const __nv_bfloat16* gq = g_qh + (size_t)(b * TT + m0) * NE + h * 128;
        const __nv_bfloat16* gl = g_ql + (size_t)(b * TT + m0) * NE + h * 128;
#pragma unroll
        for (int i = 0; i < 8; i++) {
            int f = i * 256 + tid;
            int r = f >> 4;
            int c = f & 15;
            uint4 vh = *(const uint4*)(gq + (size_t)r * NE + c * 8);
            uint4 vl = *(const uint4*)(gl + (size_t)r * NE + c * 8);
            *(uint4*)(fsm + r * QROWB + c * 16) = vh;
            *(uint4*)(fsm + QTILE_B + r * QROWB + c * 16) = vl;
        }
    }

    auto load_stage = [&](int s, int kb) {
        uint32_t st = sb + 2 * QTILE_B + s * FSTAGE_B;
        const __nv_bfloat16* kh = g_kh + (size_t)(b * TT + kb * CKEYS) * HD;
        const __nv_bfloat16* kl = g_kl + (size_t)(b * TT + kb * CKEYS) * HD;
#pragma unroll
        for (int i = 0; i < 4; i++) {
            int f = i * 256 + tid;
            int r = f >> 4;
            int c = f & 15;
            CP_ASYNC16(st + r * KROWB + c * 16, kh + (size_t)r * HD + c * 8);
            CP_ASYNC16(st + KTILE_B + r * KROWB + c * 16, kl + (size_t)r * HD + c * 8);
        }
        const __nv_bfloat16* vh = g_vth + (size_t)b * HD * TT + kb * CKEYS;
        const __nv_bfloat16* vl = g_vtl + (size_t)b * HD * TT + kb * CKEYS;
#pragma unroll
        for (int i = 0; i < 4; i++) {
            int f = i * 256 + tid;
            int r = f >> 3;
            int c = f & 7;
            CP_ASYNC16(st + 2 * KTILE_B + r * VROWB + c * 16,
                       vh + (size_t)r * TT + c * 8);
            CP_ASYNC16(st + 2 * KTILE_B + VTILE_B + r * VROWB + c * 16,
                       vl + (size_t)r * TT + c * 8);
        }
        asm volatile("cp.async.commit_group;" ::: "memory");
    };

    float oacc[16][4];
#pragma unroll
    for (int t = 0; t < 16; t++)
#pragma unroll
        for (int j = 0; j < 4; j++) oacc[t][j] = 0.0f;
    float m_i[2] = {-INFINITY, -INFINITY};
    float l_i[2] = {0.0f, 0.0f};

    load_stage(0, 0);

    for (int kb = 0; kb < NCH; kb++) {
        const int s = kb & 1;
        if (kb + 1 < NCH) {
            load_stage((kb + 1) & 1, kb + 1);
            asm volatile("cp.async.wait_group 1;" ::: "memory");
        } else {
            asm volatile("cp.async.wait_group 0;" ::: "memory");
        }
        __syncthreads();

        const uint32_t st = sb + 2 * QTILE_B + s * FSTAGE_B;
        const int mat = lane >> 3;

        float sfr[8][4];
#pragma unroll
        for (int t = 0; t < 8; t++)
#pragma unroll
            for (int j = 0; j < 4; j++) sfr[t][j] = 0.0f;

#pragma unroll
        for (int ks = 0; ks < 8; ks++) {
            uint32_t ao = (warp * 16 + (lane & 15)) * QROWB
                        + ks * 32 + (lane >> 4) * 16;
            uint32_t ah[4], al[4];
            ldsm_x4(ah[0], ah[1], ah[2], ah[3], sb + ao);
            ldsm_x4(al[0], al[1], al[2], al[3], sb + QTILE_B + ao);

            uint32_t bo = ((mat >> 1) * 8 + (lane & 7)) * KROWB
                        + ks * 32 + (mat & 1) * 16;
            uint32_t bh[8][2], bl[8][2];
#pragma unroll
            for (int g = 0; g < 4; g++) {
                uint32_t o = g * 16 * KROWB + bo;
                ldsm_x4(bh[2 * g][0], bh[2 * g][1], bh[2 * g + 1][0],
                        bh[2 * g + 1][1], st + o);
                ldsm_x4(bl[2 * g][0], bl[2 * g][1], bl[2 * g + 1][0],
                        bl[2 * g + 1][1], st + KTILE_B + o);
            }
#pragma unroll
            for (int nj = 0; nj < 8; nj++) {
                mma_16816(sfr[nj], ah, bh[nj]);
                mma_16816(sfr[nj], ah, bl[nj]);
                mma_16816(sfr[nj], al, bh[nj]);
            }
        }

#pragma unroll
        for (int half = 0; half < 2; half++) {
            float mx = -INFINITY;
#pragma unroll
            for (int nj = 0; nj < 8; nj++)
                mx = fmaxf(mx, fmaxf(sfr[nj][2 * half], sfr[nj][2 * half + 1]));
            mx = fmaxf(mx, __shfl_xor_sync(0xffffffffu, mx, 1));
            mx = fmaxf(mx, __shfl_xor_sync(0xffffffffu, mx, 2));
            float mn = fmaxf(m_i[half], mx);
            float corr = __expf(m_i[half] - mn);
            m_i[half] = mn;
            float sum = 0.0f;
#pragma unroll
            for (int nj = 0; nj < 8; nj++) {
                float p0 = __expf(sfr[nj][2 * half] - mn);
                float p1 = __expf(sfr[nj][2 * half + 1] - mn);
                sfr[nj][2 * half] = p0;
                sfr[nj][2 * half + 1] = p1;
                sum += p0 + p1;
            }
            sum += __shfl_xor_sync(0xffffffffu, sum, 1);
            sum += __shfl_xor_sync(0xffffffffu, sum, 2);
            l_i[half] = l_i[half] * corr + sum;
#pragma unroll
            for (int nt = 0; nt < 16; nt++) {
                oacc[nt][2 * half] *= corr;
                oacc[nt][2 * half + 1] *= corr;
            }
        }

        const uint32_t vbh = st + 2 * KTILE_B;
        const uint32_t vbl = vbh + VTILE_B;
#pragma unroll
        for (int kk = 0; kk < 4; kk++) {
            uint32_t ph[4], pl[4];
            split2(sfr[2 * kk][0], sfr[2 * kk][1], ph[0], pl[0]);
            split2(sfr[2 * kk][2], sfr[2 * kk][3], ph[1], pl[1]);
            split2(sfr[2 * kk + 1][0], sfr[2 * kk + 1][1], ph[2], pl[2]);
            split2(sfr[2 * kk + 1][2], sfr[2 * kk + 1][3], ph[3], pl[3]);

            uint32_t bo = ((mat >> 1) * 8 + (lane & 7)) * VROWB
                        + kk * 32 + (mat & 1) * 16;
#pragma unroll
            for (int g = 0; g < 8; g++) {
                uint32_t o = g * 16 * VROWB + bo;
                uint32_t vh0[2], vh1[2], vl0[2], vl1[2];
                ldsm_x4(vh0[0], vh0[1], vh1[0], vh1[1], vbh + o);
                ldsm_x4(vl0[0], vl0[1], vl1[0], vl1[1], vbl + o);
                mma_16816(oacc[2 * g], ph, vh0);
                mma_16816(oacc[2 * g], pl, vh0);
                mma_16816(oacc[2 * g], ph, vl0);
                mma_16816(oacc[2 * g + 1], ph, vh1);
                mma_16816(oacc[2 * g + 1], pl, vh1);
                mma_16816(oacc[2 * g + 1], ph, vl1);
            }
        }
        __syncthreads();
    }

#pragma unroll
    for (int half = 0; half < 2; half++) {
        const int row = m0 + warp * 16 + (lane >> 2) + half * 8;
        const float inv = 1.0f / l_i[half];
        size_t off = (size_t)(b * TT + row) * NE + h * 128 + (lane & 3) * 2;
#pragma unroll
        for (int nt = 0; nt < 16; nt++) {
            uint32_t hw, lw;
            split2(oacc[nt][2 * half] * inv, oacc[nt][2 * half + 1] * inv, hw, lw);
            *(uint32_t*)&g_ath[off + nt * 8] = hw;
            *(uint32_t*)&g_atl[off + nt * 8] = lw;
        }
    }
}

// ---------------------------------------------------------------------------
extern "C" void kernel_launch(void* const* d_in, const int* in_sizes, int n_in,
                              void* d_out, int out_size) {
    const float* x      = (const float*)d_in[0];
    const float* w_attn = (const float*)d_in[1];
    const float* w_out  = (const float*)d_in[2];
    float* out = (float*)d_out;

    float* qkv = nullptr;
    __nv_bfloat16 *xh, *xl, *wah, *wal, *woh, *wol, *ath, *atl;
    cudaGetSymbolAddress((void**)&qkv, g_qkv);
    cudaGetSymbolAddress((void**)&xh, g_xh);
    cudaGetSymbolAddress((void**)&xl, g_xl);
    cudaGetSymbolAddress((void**)&wah, g_wah);
    cudaGetSymbolAddress((void**)&wal, g_wal);
    cudaGetSymbolAddress((void**)&woh, g_woh);
    cudaGetSymbolAddress((void**)&wol, g_wol);
    cudaGetSymbolAddress((void**)&ath, g_ath);
    cudaGetSymbolAddress((void**)&atl, g_atl);

    cudaFuncSetAttribute(gemm_bf16x3,
                         cudaFuncAttributeMaxDynamicSharedMemorySize, GEMM_SMEM);
    cudaFuncSetAttribute(mqa_flash_mma,
                         cudaFuncAttributeMaxDynamicSharedMemorySize, FLASH_SMEM);

    // 0) split inputs
    split_kernel<<<(MROWS * NE / 4 + 255) / 256, 256>>>(x, xh, xl, MROWS * NE / 4);
    split_kernel<<<(QKV_LD * NE / 4 + 255) / 256, 256>>>(w_attn, wah, wal, QKV_LD * NE / 4);
    split_kernel<<<(NE * NE / 4 + 255) / 256, 256>>>(w_out, woh, wol, NE * NE / 4);

    // 1) qkv = x @ w_attn^T
    gemm_bf16x3<<<dim3(QKV_LD / 128, MROWS / 128), 256, GEMM_SMEM>>>(
        xh, xl, wah, wal, qkv, QKV_LD);

    // 2) fused RoPE + Q/K split (bf16 hi/lo out; no fp32 writeback)
    rope_split_kernel<<<MROWS, 64>>>();

    // 3) V transpose + split
    v_split_t<<<BB * (TT / 64), 256>>>();

    // 4) attention (mma) -> att hi/lo bf16
    mqa_flash_mma<<<dim3(TT / 128, NH, BB), 256, FLASH_SMEM>>>();

    // 5) out = att @ w_out^T
    gemm_bf16x3<<<dim3(NE / 128, MROWS / 128), 256, GEMM_SMEM>>>(
        ath, atl, woh, wol, out, NE);
}